// round 13
// baseline (speedup 1.0000x reference)
#include <cuda_runtime.h>
#include <cuda_bf16.h>
#include <math.h>
#include <stdint.h>
#include <stddef.h>

#define Bsz 64
#define Tt  100
#define Ss  400
#define Ee  512
#define Hh  1024
#define Kk  512
#define Vv  34

#define NCTA 128

typedef __nv_bfloat16 bf16;

// ---------------- static device scratch ----------------
__device__ __align__(256) bf16  g_wcat[3][(size_t)4096 * 2048];  // bf16 weights, concat ih|hh
__device__ __align__(256) bf16  g_xs[(size_t)Tt * Bsz * Ee];     // bf16 embedded inputs
__device__ __align__(256) bf16  g_h1b[2][Bsz * Hh];              // bf16 h states (ping-pong)
__device__ __align__(256) bf16  g_h2b[2][Bsz * Hh];
__device__ __align__(256) bf16  g_h3b[2][Bsz * Hh];
__device__ __align__(256) float g_h3f[2][Bsz * Hh];              // fp32 h3 (for proj)
__device__ __align__(256) float g_c1[Bsz * Hh];
__device__ __align__(256) float g_c2[Bsz * Hh];
__device__ __align__(256) float g_c3[Bsz * Hh];
__device__ __align__(256) bf16  g_ctxb[Bsz * Kk];                // bf16 (gemm input)
__device__ __align__(256) float g_q[Bsz * Kk];
__device__ __align__(256) float g_energy[Bsz * Ss];

// grid barrier state (monotonic epoch; survives replays correctly)
__device__ unsigned g_cnt = 0;
__device__ unsigned g_epoch = 0;

// ---------------- helpers ----------------
__device__ __forceinline__ void mma_bf16(float* c,
    uint32_t a0, uint32_t a1, uint32_t a2, uint32_t a3,
    uint32_t b0, uint32_t b1) {
    asm volatile(
        "mma.sync.aligned.m16n8k16.row.col.f32.bf16.bf16.f32 "
        "{%0,%1,%2,%3},{%4,%5,%6,%7},{%8,%9},{%0,%1,%2,%3};\n"
        : "+f"(c[0]), "+f"(c[1]), "+f"(c[2]), "+f"(c[3])
        : "r"(a0), "r"(a1), "r"(a2), "r"(a3), "r"(b0), "r"(b1));
}

__device__ __forceinline__ void ldsm4(uint32_t& r0, uint32_t& r1,
                                      uint32_t& r2, uint32_t& r3, uint32_t addr) {
    asm volatile("ldmatrix.sync.aligned.m8n8.x4.shared.b16 {%0,%1,%2,%3}, [%4];"
        : "=r"(r0), "=r"(r1), "=r"(r2), "=r"(r3) : "r"(addr));
}

// ---- mbarrier + bulk-copy (TMA-1D) primitives ----
__device__ __forceinline__ void mbar_init(uint32_t mbar, uint32_t count) {
    asm volatile("mbarrier.init.shared.b64 [%0], %1;" :: "r"(mbar), "r"(count) : "memory");
}
__device__ __forceinline__ void fence_proxy_async_cta() {
    asm volatile("fence.proxy.async.shared::cta;" ::: "memory");
}
__device__ __forceinline__ void mbar_expect_tx(uint32_t mbar, uint32_t bytes) {
    asm volatile("mbarrier.arrive.expect_tx.shared.b64 _, [%0], %1;"
                 :: "r"(mbar), "r"(bytes) : "memory");
}
__device__ __forceinline__ void bulk_g2s(uint32_t dst, const void* src,
                                         uint32_t bytes, uint32_t mbar) {
    asm volatile(
        "cp.async.bulk.shared::cta.global.mbarrier::complete_tx::bytes "
        "[%0], [%1], %2, [%3];"
        :: "r"(dst), "l"(src), "r"(bytes), "r"(mbar) : "memory");
}
__device__ __forceinline__ void bulk_g2s_ef(uint32_t dst, const void* src,
                                            uint32_t bytes, uint32_t mbar,
                                            uint64_t pol) {
    asm volatile(
        "cp.async.bulk.shared::cta.global.mbarrier::complete_tx::bytes.L2::cache_hint "
        "[%0], [%1], %2, [%3], %4;"
        :: "r"(dst), "l"(src), "r"(bytes), "r"(mbar), "l"(pol) : "memory");
}
__device__ __forceinline__ void mbar_wait(uint32_t mbar, uint32_t parity) {
    uint32_t done;
    asm volatile(
        "{\n\t.reg .pred p;\n\t"
        "mbarrier.try_wait.parity.acquire.cta.shared::cta.b64 p, [%1], %2;\n\t"
        "selp.b32 %0, 1, 0, p;\n\t}"
        : "=r"(done) : "r"(mbar), "r"(parity) : "memory");
    if (!done) {
        asm volatile(
            "{\n\t.reg .pred P1;\n\t"
            "WAIT_LOOP_%=:\n\t"
            "mbarrier.try_wait.parity.acquire.cta.shared::cta.b64 P1, [%0], %1, 0x989680;\n\t"
            "@P1 bra.uni WAIT_DONE_%=;\n\t"
            "bra.uni WAIT_LOOP_%=;\n\t"
            "WAIT_DONE_%=:\n\t}"
            :: "r"(mbar), "r"(parity) : "memory");
    }
}

// grid-wide barrier: release (threadfence) + counting arrive + epoch spin + acquire.
__device__ __forceinline__ void grid_bar(unsigned target) {
    __threadfence();
    __syncthreads();
    if (threadIdx.x == 0) {
        unsigned n = atomicAdd(&g_cnt, 1u);
        if (n == NCTA - 1u) {
            g_cnt = 0;
            __threadfence();
            atomicAdd(&g_epoch, 1u);
        } else {
            while (*(volatile unsigned*)&g_epoch < target) __nanosleep(32);
        }
        __threadfence();       // acquire: invalidates this SM's L1D
    }
    __syncthreads();
}

// ---------------- LSTM tiling constants ----------------
#define BK 64
#define STAGES 7
#define PFD 5
#define APAD 72
#define A_ST (64 * APAD)
#define B_ST (32 * APAD)
#define STAGE_ELE (A_ST + B_ST)
#define MBAR_OFF (STAGES * STAGE_ELE * 2)     /* 96768 bytes */
#define SMEM_TOTAL (MBAR_OFF + 64)

struct SegInfo { const bf16* p; int stride; };

__device__ __forceinline__ SegInfo a_seg(int cell, int p, int t, int seg) {
    SegInfo r;
    if (cell == 0) {
        if (seg == 0)      { r.p = g_xs + (size_t)t * Bsz * Ee; r.stride = Ee; }
        else if (seg == 1) { r.p = g_ctxb;                      r.stride = Kk; }
        else               { r.p = g_h1b[p] + (seg - 2) * 512;  r.stride = Hh; }
    } else if (cell == 1) {
        if (seg < 2) { r.p = g_h1b[1 - p] + seg * 512;       r.stride = Hh; }
        else         { r.p = g_h2b[p]     + (seg - 2) * 512; r.stride = Hh; }
    } else {
        if (seg < 2) { r.p = g_h2b[1 - p] + seg * 512;       r.stride = Hh; }
        else         { r.p = g_h3b[p]     + (seg - 2) * 512; r.stride = Hh; }
    }
    return r;
}

// ---------------- lstm phase (runs on all 128 CTAs) ----------------
// pk = 3*t + cell: global lstm-phase counter for persistent mbarrier parity.
__device__ __forceinline__ void lstm_phase(
    char* smem_raw, int cell, int t, int pk,
    const float* __restrict__ b_ih, const float* __restrict__ b_hh)
{
    bf16* smem = (bf16*)smem_raw;
    const int p = t & 1;
    const int tid = threadIdx.x;
    const int lane = tid & 31;
    const int warp = tid >> 5;
    const int wm = warp & 3;
    const int wn = warp >> 2;
    const int j0 = blockIdx.x * 8;
    const bf16* __restrict__ wcat = g_wcat[cell];

    uint64_t pol;
    asm("createpolicy.fractional.L2::evict_first.b64 %0;" : "=l"(pol));

    float* c_st; bf16* h_ob; float* h_f;
    if (cell == 0)      { c_st = g_c1; h_ob = g_h1b[1 - p]; h_f = nullptr; }
    else if (cell == 1) { c_st = g_c2; h_ob = g_h2b[1 - p]; h_f = nullptr; }
    else                { c_st = g_c3; h_ob = g_h3b[1 - p]; h_f = g_h3f[1 - p]; }

    const uint32_t smem_u = (uint32_t)__cvta_generic_to_shared(smem);
    const uint32_t mbar_u = smem_u + MBAR_OFF;

    // Order prior generic smem writes (previous phase scratch) before the
    // async-proxy fills below. All threads entered via __syncthreads (grid_bar).
    fence_proxy_async_cta();

    float acc0[4] = {0.f, 0.f, 0.f, 0.f};
    float acc1[4] = {0.f, 0.f, 0.f, 0.f};

    const int NTILES = 2048 / BK;   // 32

    // one bulk op per row: threads 0..63 -> A rows, 64..95 -> B rows
    auto issue_tile = [&](int kt, int ss) {
        if (tid < 96) {
            const int k0 = kt * BK;
            const uint32_t mb = mbar_u + (uint32_t)ss * 8u;
            mbar_expect_tx(mb, 128);
            if (tid < 64) {
                SegInfo si = a_seg(cell, p, t, k0 >> 9);
                const int kin = k0 & 511;
                const bf16* src = si.p + (size_t)tid * si.stride + kin;
                uint32_t dst = smem_u + (uint32_t)(ss * STAGE_ELE + tid * APAD) * 2u;
                bulk_g2s(dst, src, 128, mb);
            } else {
                int n = tid - 64;
                int r = (n >> 3) * 1024 + j0 + (n & 7);
                const bf16* src = wcat + (size_t)r * 2048 + k0;
                uint32_t dst = smem_u + (uint32_t)(ss * STAGE_ELE + A_ST + n * APAD) * 2u;
                bulk_g2s_ef(dst, src, 128, mb, pol);
            }
        }
    };

#pragma unroll
    for (int i = 0; i < PFD; i++) issue_tile(i, i);

    const uint32_t a_lane_off =
        (uint32_t)((wm * 16 + (lane & 15)) * APAD + (lane >> 4) * 8) * 2u;
    const uint32_t b_lane_off =
        (uint32_t)((wn * 16 + ((lane >> 4) << 3) + (lane & 7)) * APAD
                   + ((lane >> 3) & 1) * 8) * 2u;

    for (int kt = 0; kt < NTILES; kt++) {
        if (kt + PFD < NTILES) issue_tile(kt + PFD, (kt + PFD) % STAGES);
        // persistent parity: stage s has c_s fills per phase (5 for s<4, 4 else)
        {
            const int s = kt % STAGES;
            const int j = kt / STAGES;
            const int cs = (s < 4) ? 5 : 4;
            mbar_wait(mbar_u + (uint32_t)s * 8u, (unsigned)((pk * cs + j) & 1));
        }
        __syncthreads();   // also bounds warp skew for stage reuse (dist 2)

        const uint32_t As_u = smem_u + (uint32_t)((kt % STAGES) * STAGE_ELE) * 2u;
        const uint32_t Bs_u = As_u + (uint32_t)A_ST * 2u;
#pragma unroll
        for (int ks = 0; ks < BK / 16; ks++) {
            const uint32_t kb2 = (uint32_t)(ks * 16) * 2u;
            uint32_t a0, a1, a2, a3, b0, b1, b2, b3;
            ldsm4(a0, a1, a2, a3, As_u + a_lane_off + kb2);
            ldsm4(b0, b1, b2, b3, Bs_u + b_lane_off + kb2);
            mma_bf16(acc0, a0, a1, a2, a3, b0, b1);
            mma_bf16(acc1, a0, a1, a2, a3, b2, b3);
        }
    }
    __syncthreads();

    float* Cs = (float*)smem_raw;
    {
        const int ar = lane >> 2;
        const int ac = lane & 3;
        int crow = wm * 16 + ar;
        int cc0 = wn * 16 + 2 * ac;
        Cs[crow * 33 + cc0]           = acc0[0];
        Cs[crow * 33 + cc0 + 1]       = acc0[1];
        Cs[(crow + 8) * 33 + cc0]     = acc0[2];
        Cs[(crow + 8) * 33 + cc0 + 1] = acc0[3];
        Cs[crow * 33 + cc0 + 8]       = acc1[0];
        Cs[crow * 33 + cc0 + 9]       = acc1[1];
        Cs[(crow + 8) * 33 + cc0 + 8] = acc1[2];
        Cs[(crow + 8) * 33 + cc0 + 9] = acc1[3];
    }
    __syncthreads();

#pragma unroll
    for (int j = 0; j < 2; j++) {
        int pr = tid + j * 256;
        int m = pr & 63;
        int jj = pr >> 6;
        int jg = j0 + jj;
        float gi = Cs[m * 33 + jj]      + b_ih[jg]        + b_hh[jg];
        float gf = Cs[m * 33 + 8 + jj]  + b_ih[1024 + jg] + b_hh[1024 + jg];
        float gg = Cs[m * 33 + 16 + jj] + b_ih[2048 + jg] + b_hh[2048 + jg];
        float go = Cs[m * 33 + 24 + jj] + b_ih[3072 + jg] + b_hh[3072 + jg];
        float si = 1.f / (1.f + expf(-gi));
        float sf = 1.f / (1.f + expf(-gf));
        float so = 1.f / (1.f + expf(-go));
        float cn = sf * c_st[(size_t)m * Hh + jg] + si * tanhf(gg);
        c_st[(size_t)m * Hh + jg] = cn;
        float hn = so * tanhf(cn);
        h_ob[(size_t)m * Hh + jg] = __float2bfloat16_rn(hn);
        if (h_f) h_f[(size_t)m * Hh + jg] = hn;
    }
}

// ---------------- the single persistent decoder kernel ----------------
__global__ void __launch_bounds__(256, 1) decoder_kernel(
    const int* __restrict__ labels, const float* __restrict__ keys,
    const float* __restrict__ values, const float* __restrict__ emb,
    const float* __restrict__ w_ih0, const float* __restrict__ w_hh0,
    const float* __restrict__ b_ih0, const float* __restrict__ b_hh0,
    const float* __restrict__ w_ih1, const float* __restrict__ w_hh1,
    const float* __restrict__ b_ih1, const float* __restrict__ b_hh1,
    const float* __restrict__ w_ih2, const float* __restrict__ w_hh2,
    const float* __restrict__ b_ih2, const float* __restrict__ b_hh2,
    const float* __restrict__ w_proj, const float* __restrict__ b_proj,
    const float* __restrict__ w_score, const float* __restrict__ b_score,
    const float* __restrict__ h0,
    float* __restrict__ out_pred, float* __restrict__ out_attn)
{
    extern __shared__ __align__(16) char smem_raw[];
    const int tid = threadIdx.x;
    const int cta = blockIdx.x;
    const int lane = tid & 31;
    const int wid = tid >> 5;

    const unsigned ep0 = *(volatile unsigned*)&g_epoch;
    unsigned nbar = 0;

    // ---- mbarrier one-time init (count = 96 producer arrivals per fill) ----
    {
        const uint32_t smem_u = (uint32_t)__cvta_generic_to_shared(smem_raw);
        if (tid < STAGES) mbar_init(smem_u + MBAR_OFF + tid * 8, 96);
        fence_proxy_async_cta();
        __syncthreads();
    }

    // ================= PREP =================
    {
        const float* wih[3] = {w_ih0, w_ih1, w_ih2};
        const float* whh[3] = {w_hh0, w_hh1, w_hh2};
        for (int r = cta; r < 3 * 4096; r += NCTA) {
            int cell = r >> 12, row = r & 4095;
            float4 va = ((const float4*)(wih[cell] + (size_t)row * 1024))[tid];
            float4 vb = ((const float4*)(whh[cell] + (size_t)row * 1024))[tid];
            __nv_bfloat162* d2 = (__nv_bfloat162*)(g_wcat[cell] + (size_t)row * 2048);
            d2[2 * tid]           = __floats2bfloat162_rn(va.x, va.y);
            d2[2 * tid + 1]       = __floats2bfloat162_rn(va.z, va.w);
            d2[512 + 2 * tid]     = __floats2bfloat162_rn(vb.x, vb.y);
            d2[512 + 2 * tid + 1] = __floats2bfloat162_rn(vb.z, vb.w);
        }
        // embedding
        for (int tb = cta; tb < Tt * Bsz; tb += NCTA) {
            int t = tb / Bsz, b = tb % Bsz;
            int lab = labels[b * Tt + t];
            if (tid < 128) {
                float4 v = ((const float4*)(emb + (size_t)lab * Ee))[tid];
                __nv_bfloat162* dst =
                    (__nv_bfloat162*)(g_xs + ((size_t)t * Bsz + b) * Ee);
                dst[2 * tid]     = __floats2bfloat162_rn(v.x, v.y);
                dst[2 * tid + 1] = __floats2bfloat162_rn(v.z, v.w);
            }
        }
        // init h/c
#pragma unroll
        for (int j = 0; j < 2; j++) {
            int i = cta * 512 + j * 256 + tid;
            float v = h0[i & (Hh - 1)];
            bf16 vb = __float2bfloat16_rn(v);
            g_h1b[0][i] = vb; g_h2b[0][i] = vb; g_h3b[0][i] = vb;
            g_h3f[0][i] = v;
            g_c1[i] = v; g_c2[i] = v; g_c3[i] = v;
        }
        // zero out_pred (atomicAdd target)
        for (int i = cta * 256 + tid; i < Bsz * Tt * Vv; i += NCTA * 256)
            out_pred[i] = 0.f;
        // ctx0
        float* red = (float*)smem_raw;
        for (int kk = 0; kk < 4; kk++) {
            int k = cta * 4 + kk;
            float s = 0.f;
            for (int i = tid; i < Hh; i += 256)
                s += h0[i] * w_proj[(size_t)k * Hh + i];
#pragma unroll
            for (int off = 16; off; off >>= 1)
                s += __shfl_xor_sync(0xffffffffu, s, off);
            if (lane == 0) red[wid] = s;
            __syncthreads();
            if (tid == 0) {
                float v = 0.f;
#pragma unroll
                for (int j = 0; j < 8; j++) v += red[j];
                red[8] = v + b_proj[k];
            }
            __syncthreads();
            float v = red[8];
            if (tid < Bsz) g_ctxb[(size_t)tid * Kk + k] = __float2bfloat16_rn(v);
            __syncthreads();
        }
    }
    grid_bar(ep0 + ++nbar);

    // ================= TIME LOOP =================
    for (int t = 0; t < Tt; t++) {
        lstm_phase(smem_raw, 0, t, 3 * t + 0, b_ih0, b_hh0);
        grid_bar(ep0 + ++nbar);
        lstm_phase(smem_raw, 1, t, 3 * t + 1, b_ih1, b_hh1);
        grid_bar(ep0 + ++nbar);
        lstm_phase(smem_raw, 2, t, 3 * t + 2, b_ih2, b_hh2);
        grid_bar(ep0 + ++nbar);

        // ---- proj: q = h3 @ w_proj^T + b_proj (kb = cta, 4 k's) ----
        {
            float* sw = (float*)smem_raw;
            const float4* wp4 = (const float4*)(w_proj + (size_t)cta * 4 * 1024);
            float4* sw4 = (float4*)sw;
#pragma unroll
            for (int j = 0; j < 4; j++) sw4[tid + j * 256] = wp4[tid + j * 256];
            __syncthreads();

            const float* h3 = g_h3f[1 - (t & 1)];
            int b = tid >> 2;
            int kl = tid & 3;
            const float4* hr = (const float4*)(h3 + (size_t)b * Hh);
            const float4* w0 = (const float4*)(sw + kl * 1024);
            float a0 = 0.f, a1 = 0.f;
#pragma unroll 4
            for (int i = 0; i < 256; i += 2) {
                float4 h4 = hr[i];
                float4 x0 = w0[i];
                a0 += h4.x * x0.x + h4.y * x0.y + h4.z * x0.z + h4.w * x0.w;
                float4 h5 = hr[i + 1];
                float4 x1 = w0[i + 1];
                a1 += h5.x * x1.x + h5.y * x1.y + h5.z * x1.z + h5.w * x1.w;
            }
            int kg = cta * 4 + kl;
            g_q[(size_t)b * Kk + kg] = a0 + a1 + b_proj[kg];
        }
        grid_bar(ep0 + ++nbar);

        // ---- energy: cta -> (b = cta&63, half = cta>>6), 200 s each ----
        {
            float* sq = (float*)smem_raw;
            const int b = cta & 63;
            const int half = cta >> 6;
            if (tid < 128)
                ((float4*)sq)[tid] = ((const float4*)(g_q + (size_t)b * Kk))[tid];
            __syncthreads();
            const float4* qr = (const float4*)sq;
            const int base = half * 200;
#pragma unroll 2
            for (int i = 0; i < 12; i++) {
                int s1 = base + wid + 16 * i;
                int s2 = s1 + 8;
                const float4* k1 = (const float4*)(keys + ((size_t)s1 * Bsz + b) * Kk);
                const float4* k2 = (const float4*)(keys + ((size_t)s2 * Bsz + b) * Kk);
                float acc1 = 0.f, acc2 = 0.f;
#pragma unroll
                for (int u = 0; u < 4; u++) {
                    float4 q4 = qr[lane + u * 32];
                    float4 a4 = k1[lane + u * 32];
                    float4 b4 = k2[lane + u * 32];
                    acc1 += a4.x * q4.x + a4.y * q4.y + a4.z * q4.z + a4.w * q4.w;
                    acc2 += b4.x * q4.x + b4.y * q4.y + b4.z * q4.z + b4.w * q4.w;
                }
#pragma unroll
                for (int off = 16; off; off >>= 1) {
                    acc1 += __shfl_xor_sync(0xffffffffu, acc1, off);
                    acc2 += __shfl_xor_sync(0xffffffffu, acc2, off);
                }
                if (lane == 0) {
                    g_energy[b * Ss + s1] = acc1;
                    g_energy[b * Ss + s2] = acc2;
                }
            }
            {   // tail: s = base + 192 + wid
                int s = base + 192 + wid;
                const float4* kr = (const float4*)(keys + ((size_t)s * Bsz + b) * Kk);
                float acc = 0.f;
#pragma unroll
                for (int u = 0; u < 4; u++) {
                    float4 k4 = kr[lane + u * 32];
                    float4 q4 = qr[lane + u * 32];
                    acc += k4.x * q4.x + k4.y * q4.y + k4.z * q4.z + k4.w * q4.w;
                }
#pragma unroll
                for (int off = 16; off; off >>= 1)
                    acc += __shfl_xor_sync(0xffffffffu, acc, off);
                if (lane == 0) g_energy[b * Ss + s] = acc;
            }
            __syncthreads();
        }
        grid_bar(ep0 + ++nbar);

        // ---- softmax + ctx + partial score (cta -> b, half k-range) ----
        {
            float* sattn = (float*)smem_raw;          // 400
            float* sctx  = sattn + Ss;                 // 256
            float* sqh   = sctx + 256;                 // 256
            float* red   = sqh + 256;                  // 9
            const int b = cta & 63;
            const int half = cta >> 6;
            const int koff = half * 256;

            for (int s = tid; s < Ss; s += 256) sattn[s] = g_energy[b * Ss + s];
            sqh[tid] = g_q[(size_t)b * Kk + koff + tid];
            __syncthreads();

            // max
            float m = -3.4e38f;
            for (int s = tid; s < Ss; s += 256) m = fmaxf(m, sattn[s]);
#pragma unroll
            for (int off = 16; off; off >>= 1)
                m = fmaxf(m, __shfl_xor_sync(0xffffffffu, m, off));
            if (lane == 0) red[wid] = m;
            __syncthreads();
            if (wid == 0) {
                float v = (lane < 8) ? red[lane] : -3.4e38f;
#pragma unroll
                for (int off = 4; off; off >>= 1)
                    v = fmaxf(v, __shfl_xor_sync(0xffffffffu, v, off));
                if (lane == 0) red[8] = v;
            }
            __syncthreads();
            const float mx = red[8];
            __syncthreads();

            // exp + sum
            float sum = 0.f;
            for (int s = tid; s < Ss; s += 256) {
                float e = expf(sattn[s] - mx);
                sattn[s] = e;
                sum += e;
            }
#pragma unroll
            for (int off = 16; off; off >>= 1)
                sum += __shfl_xor_sync(0xffffffffu, sum, off);
            if (lane == 0) red[wid] = sum;
            __syncthreads();
            if (wid == 0) {
                float v = (lane < 8) ? red[lane] : 0.f;
#pragma unroll
                for (int off = 4; off; off >>= 1)
                    v += __shfl_xor_sync(0xffffffffu, v, off);
                if (lane == 0) red[8] = v;
            }
            __syncthreads();
            const float inv = 1.f / red[8];
            for (int s = tid; s < Ss; s += 256) sattn[s] *= inv;
            __syncthreads();

            // write attention output (this CTA's half of S)
            for (int s = half * 200 + tid; s < half * 200 + 200; s += 256)
                out_attn[((size_t)b * Tt + t) * Ss + s] = sattn[s];

            // ctx for k in [koff, koff+256), fp32 values
            {
                const int k = koff + tid;
                const size_t base = (size_t)b * Kk + k;
                const size_t str = (size_t)Bsz * Kk;
                float a0 = 0.f, a1 = 0.f, a2 = 0.f, a3 = 0.f;
                for (int s = 0; s < Ss; s += 4) {
                    a0 += sattn[s]     * values[base + (size_t)s * str];
                    a1 += sattn[s + 1] * values[base + (size_t)(s + 1) * str];
                    a2 += sattn[s + 2] * values[base + (size_t)(s + 2) * str];
                    a3 += sattn[s + 3] * values[base + (size_t)(s + 3) * str];
                }
                float r = (a0 + a1) + (a2 + a3);
                sctx[tid] = r;
                g_ctxb[(size_t)b * Kk + k] = __float2bfloat16_rn(r);
            }
            __syncthreads();

            // partial score over this k-half; combine across halves via atomicAdd
            for (int v = wid; v < Vv; v += 8) {
                const float* wr = w_score + (size_t)v * (2 * Kk);
                float acc = 0.f;
                for (int i = lane; i < 256; i += 32)
                    acc += sqh[i] * wr[koff + i] + sctx[i] * wr[Kk + koff + i];
#pragma unroll
                for (int off = 16; off; off >>= 1)
                    acc += __shfl_xor_sync(0xffffffffu, acc, off);
                if (lane == 0) {
                    float add = acc + (half == 0 ? b_score[v] : 0.f);
                    atomicAdd(&out_pred[((size_t)b * Tt + t) * Vv + v], add);
                }
            }
            __syncthreads();
        }
        grid_bar(ep0 + ++nbar);
    }
}

// ---------------- launch ----------------
extern "C" void kernel_launch(void* const* d_in, const int* in_sizes, int n_in,
                              void* d_out, int out_size) {
    const int*   labels  = (const int*)  d_in[0];
    const float* keys    = (const float*)d_in[1];
    const float* values  = (const float*)d_in[2];
    const float* emb     = (const float*)d_in[3];
    const float* w_ih0   = (const float*)d_in[4];
    const float* w_hh0   = (const float*)d_in[5];
    const float* b_ih0   = (const float*)d_in[6];
    const float* b_hh0   = (const float*)d_in[7];
    const float* w_ih1   = (const float*)d_in[8];
    const float* w_hh1   = (const float*)d_in[9];
    const float* b_ih1   = (const float*)d_in[10];
    const float* b_hh1   = (const float*)d_in[11];
    const float* w_ih2   = (const float*)d_in[12];
    const float* w_hh2   = (const float*)d_in[13];
    const float* b_ih2   = (const float*)d_in[14];
    const float* b_hh2   = (const float*)d_in[15];
    const float* w_proj  = (const float*)d_in[16];
    const float* b_proj  = (const float*)d_in[17];
    const float* w_score = (const float*)d_in[18];
    const float* b_score = (const float*)d_in[19];
    const float* h0      = (const float*)d_in[20];

    float* out_pred = (float*)d_out;
    float* out_attn = out_pred + (size_t)Bsz * Tt * Vv;

    static int configured = 0;
    if (!configured) {
        cudaFuncSetAttribute(decoder_kernel,
                             cudaFuncAttributeMaxDynamicSharedMemorySize, SMEM_TOTAL);
        configured = 1;
    }

    decoder_kernel<<<NCTA, 256, SMEM_TOTAL>>>(
        labels, keys, values, emb,
        w_ih0, w_hh0, b_ih0, b_hh0,
        w_ih1, w_hh1, b_ih1, b_hh1,
        w_ih2, w_hh2, b_ih2, b_hh2,
        w_proj, b_proj, w_score, b_score, h0,
        out_pred, out_attn);
}

// round 14
// speedup vs baseline: 1.7762x; 1.7762x over previous
#include <cuda_runtime.h>
#include <cuda_bf16.h>
#include <math.h>
#include <stdint.h>
#include <stddef.h>

#define Bsz 64
#define Tt  100
#define Ss  400
#define Ee  512
#define Hh  1024
#define Kk  512
#define Vv  34

#define NCTA 128

typedef __nv_bfloat16 bf16;

// ---------------- packed (pre-swizzled) operand storage ----------------
// Tile = 64 rows x 64 bf16 cols = 8192 B (A) or 32 rows x 64 = 4096 B (B).
// Byte offset within tile: o = row*128 + col*2, stored at o ^ ((row&7)<<4).
__device__ __align__(256) bf16 g_wP[(size_t)3 * 128 * 32 * 2048];   // 48 MB: [cell][cta][kt] 4096B tiles
__device__ __align__(256) bf16 g_xsP[(size_t)Tt * 8 * 4096];        // [t][kt] 8192B tiles
__device__ __align__(256) bf16 g_ctxP[8 * 4096];                    // [kt]
__device__ __align__(256) bf16 g_h1P[2][16 * 4096];                 // [pp][kt]
__device__ __align__(256) bf16 g_h2P[2][16 * 4096];
__device__ __align__(256) bf16 g_h3P[2][16 * 4096];
__device__ __align__(256) float g_h3f[2][Bsz * Hh];                 // fp32 h3 (for proj)
__device__ __align__(256) float g_c1[Bsz * Hh];
__device__ __align__(256) float g_c2[Bsz * Hh];
__device__ __align__(256) float g_c3[Bsz * Hh];
__device__ __align__(256) float g_q[Bsz * Kk];
__device__ __align__(256) float g_energy[Bsz * Ss];

// grid barrier state
__device__ unsigned g_cnt = 0;
__device__ unsigned g_epoch = 0;

// ---------------- helpers ----------------
__device__ __forceinline__ void mma_bf16(float* c,
    uint32_t a0, uint32_t a1, uint32_t a2, uint32_t a3,
    uint32_t b0, uint32_t b1) {
    asm volatile(
        "mma.sync.aligned.m16n8k16.row.col.f32.bf16.bf16.f32 "
        "{%0,%1,%2,%3},{%4,%5,%6,%7},{%8,%9},{%0,%1,%2,%3};\n"
        : "+f"(c[0]), "+f"(c[1]), "+f"(c[2]), "+f"(c[3])
        : "r"(a0), "r"(a1), "r"(a2), "r"(a3), "r"(b0), "r"(b1));
}

__device__ __forceinline__ void ldsm4(uint32_t& r0, uint32_t& r1,
                                      uint32_t& r2, uint32_t& r3, uint32_t addr) {
    asm volatile("ldmatrix.sync.aligned.m8n8.x4.shared.b16 {%0,%1,%2,%3}, [%4];"
        : "=r"(r0), "=r"(r1), "=r"(r2), "=r"(r3) : "r"(addr));
}

__device__ __forceinline__ void mbar_init(uint32_t mbar, uint32_t count) {
    asm volatile("mbarrier.init.shared.b64 [%0], %1;" :: "r"(mbar), "r"(count) : "memory");
}
__device__ __forceinline__ void fence_proxy_async_cta() {
    asm volatile("fence.proxy.async.shared::cta;" ::: "memory");
}
__device__ __forceinline__ void mbar_expect_tx(uint32_t mbar, uint32_t bytes) {
    asm volatile("mbarrier.arrive.expect_tx.shared.b64 _, [%0], %1;"
                 :: "r"(mbar), "r"(bytes) : "memory");
}
__device__ __forceinline__ void bulk_g2s(uint32_t dst, const void* src,
                                         uint32_t bytes, uint32_t mbar) {
    asm volatile(
        "cp.async.bulk.shared::cta.global.mbarrier::complete_tx::bytes "
        "[%0], [%1], %2, [%3];"
        :: "r"(dst), "l"(src), "r"(bytes), "r"(mbar) : "memory");
}
__device__ __forceinline__ void bulk_g2s_ef(uint32_t dst, const void* src,
                                            uint32_t bytes, uint32_t mbar,
                                            uint64_t pol) {
    asm volatile(
        "cp.async.bulk.shared::cta.global.mbarrier::complete_tx::bytes.L2::cache_hint "
        "[%0], [%1], %2, [%3], %4;"
        :: "r"(dst), "l"(src), "r"(bytes), "r"(mbar), "l"(pol) : "memory");
}
__device__ __forceinline__ void mbar_wait(uint32_t mbar, uint32_t parity) {
    uint32_t done;
    asm volatile(
        "{\n\t.reg .pred p;\n\t"
        "mbarrier.try_wait.parity.acquire.cta.shared::cta.b64 p, [%1], %2;\n\t"
        "selp.b32 %0, 1, 0, p;\n\t}"
        : "=r"(done) : "r"(mbar), "r"(parity) : "memory");
    if (!done) {
        asm volatile(
            "{\n\t.reg .pred P1;\n\t"
            "WAIT_LOOP_%=:\n\t"
            "mbarrier.try_wait.parity.acquire.cta.shared::cta.b64 P1, [%0], %1, 0x989680;\n\t"
            "@P1 bra.uni WAIT_DONE_%=;\n\t"
            "bra.uni WAIT_LOOP_%=;\n\t"
            "WAIT_DONE_%=:\n\t}"
            :: "r"(mbar), "r"(parity) : "memory");
    }
}

__device__ __forceinline__ void grid_bar(unsigned target) {
    __threadfence();
    __syncthreads();
    if (threadIdx.x == 0) {
        unsigned n = atomicAdd(&g_cnt, 1u);
        if (n == NCTA - 1u) {
            g_cnt = 0;
            __threadfence();
            atomicAdd(&g_epoch, 1u);
        } else {
            while (*(volatile unsigned*)&g_epoch < target) __nanosleep(32);
        }
        __threadfence();
    }
    __syncthreads();
}

// ---------------- LSTM tiling constants ----------------
#define STAGES 7
#define PFD 5
#define A_BYTES 8192
#define B_BYTES 4096
#define STAGE_BYTES (A_BYTES + B_BYTES)       /* 12288 */
#define MBAR_OFF (STAGES * STAGE_BYTES)       /* 86016 */
#define SMEM_TOTAL (MBAR_OFF + 64)

// ---------------- lstm phase ----------------
// pk = 3*t + cell: global lstm-phase counter for persistent mbarrier parity.
__device__ __forceinline__ void lstm_phase(
    char* smem_raw, int cell, int t, int pk,
    const float* __restrict__ b_ih, const float* __restrict__ b_hh)
{
    const int p = t & 1;
    const int tid = threadIdx.x;
    const int lane = tid & 31;
    const int warp = tid >> 5;
    const int wm = warp & 3;
    const int wn = warp >> 2;
    const int cta = blockIdx.x;
    const int j0 = cta * 8;

    uint64_t pol;
    asm("createpolicy.fractional.L2::evict_first.b64 %0;" : "=l"(pol));

    float* c_st; bf16* hP; float* h_f;
    if (cell == 0)      { c_st = g_c1; hP = g_h1P[1 - p]; h_f = nullptr; }
    else if (cell == 1) { c_st = g_c2; hP = g_h2P[1 - p]; h_f = nullptr; }
    else                { c_st = g_c3; hP = g_h3P[1 - p]; h_f = g_h3f[1 - p]; }

    const uint32_t smem_u = (uint32_t)__cvta_generic_to_shared(smem_raw);
    const uint32_t mbar_u = smem_u + MBAR_OFF;

    // Order prior generic smem writes before async-proxy fills of same bytes.
    fence_proxy_async_cta();
    __syncthreads();

    float acc0[4] = {0.f, 0.f, 0.f, 0.f};
    float acc1[4] = {0.f, 0.f, 0.f, 0.f};

    const int NTILES = 32;

    // A-source tile (8192 B contiguous, pre-swizzled)
    auto a_src = [&](int kt) -> const char* {
        if (cell == 0) {
            if (kt < 8)  return (const char*)g_xsP + ((size_t)t * 8 + kt) * A_BYTES;
            if (kt < 16) return (const char*)g_ctxP + (size_t)(kt - 8) * A_BYTES;
            return (const char*)g_h1P[p] + (size_t)(kt - 16) * A_BYTES;
        } else if (cell == 1) {
            return kt < 16 ? (const char*)g_h1P[1 - p] + (size_t)kt * A_BYTES
                           : (const char*)g_h2P[p] + (size_t)(kt - 16) * A_BYTES;
        }
        return kt < 16 ? (const char*)g_h2P[1 - p] + (size_t)kt * A_BYTES
                       : (const char*)g_h3P[p] + (size_t)(kt - 16) * A_BYTES;
    };

    // stage fill: 2 bulk ops, issued by thread 0
    auto issue_tile = [&](int kt, int ss) {
        if (tid == 0) {
            const uint32_t mb = mbar_u + (uint32_t)ss * 8u;
            const uint32_t sb = smem_u + (uint32_t)ss * STAGE_BYTES;
            mbar_expect_tx(mb, STAGE_BYTES);
            bulk_g2s(sb, a_src(kt), A_BYTES, mb);
            const char* wsrc = (const char*)g_wP
                + ((size_t)(cell * 128 + cta) * 32 + kt) * B_BYTES;
            bulk_g2s_ef(sb + A_BYTES, wsrc, B_BYTES, mb, pol);
        }
    };

#pragma unroll
    for (int i = 0; i < PFD; i++) issue_tile(i, i);

    // ldmatrix lane addressing with baked SW128 swizzle:
    // o = row*128 + colbyte; stored at o ^ ((row&7)<<4)
    const int row_a = wm * 16 + (lane & 15);
    const uint32_t a_base = (uint32_t)(row_a * 128 + (lane >> 4) * 16);
    const uint32_t a_x = (uint32_t)(row_a & 7) << 4;
    const int row_b = wn * 16 + ((lane >> 4) << 3) + (lane & 7);
    const uint32_t b_base = (uint32_t)(row_b * 128 + ((lane >> 3) & 1) * 16);
    const uint32_t b_x = (uint32_t)(row_b & 7) << 4;

    for (int kt = 0; kt < NTILES; kt++) {
        if (kt + PFD < NTILES) issue_tile(kt + PFD, (kt + PFD) % STAGES);
        {   // persistent parity: stage s has cs fills per phase (5 for s<4, 4 else)
            const int s = kt % STAGES;
            const int j = kt / STAGES;
            const int cs = (s < 4) ? 5 : 4;
            mbar_wait(mbar_u + (uint32_t)s * 8u, (unsigned)((pk * cs + j) & 1));
        }
        __syncthreads();   // bounds warp skew for stage reuse (dist 2)

        const uint32_t As_u = smem_u + (uint32_t)((kt % STAGES) * STAGE_BYTES);
        const uint32_t Bs_u = As_u + A_BYTES;
#pragma unroll
        for (int ks = 0; ks < 4; ks++) {
            const uint32_t kso = (uint32_t)(ks * 32);
            uint32_t a0, a1, a2, a3, b0, b1, b2, b3;
            ldsm4(a0, a1, a2, a3, As_u + ((a_base + kso) ^ a_x));
            ldsm4(b0, b1, b2, b3, Bs_u + ((b_base + kso) ^ b_x));
            mma_bf16(acc0, a0, a1, a2, a3, b0, b1);
            mma_bf16(acc1, a0, a1, a2, a3, b2, b3);
        }
    }
    __syncthreads();

    float* Cs = (float*)smem_raw;
    {
        const int ar = lane >> 2;
        const int ac = lane & 3;
        int crow = wm * 16 + ar;
        int cc0 = wn * 16 + 2 * ac;
        Cs[crow * 33 + cc0]           = acc0[0];
        Cs[crow * 33 + cc0 + 1]       = acc0[1];
        Cs[(crow + 8) * 33 + cc0]     = acc0[2];
        Cs[(crow + 8) * 33 + cc0 + 1] = acc0[3];
        Cs[crow * 33 + cc0 + 8]       = acc1[0];
        Cs[crow * 33 + cc0 + 9]       = acc1[1];
        Cs[(crow + 8) * 33 + cc0 + 8] = acc1[2];
        Cs[(crow + 8) * 33 + cc0 + 9] = acc1[3];
    }
    __syncthreads();

    const int hchunk = cta >> 3;                 // (j0+jj)>>6, jj<8
#pragma unroll
    for (int j = 0; j < 2; j++) {
        int pr = tid + j * 256;
        int m = pr & 63;
        int jj = pr >> 6;
        int jg = j0 + jj;
        float gi = Cs[m * 33 + jj]      + b_ih[jg]        + b_hh[jg];
        float gf = Cs[m * 33 + 8 + jj]  + b_ih[1024 + jg] + b_hh[1024 + jg];
        float gg = Cs[m * 33 + 16 + jj] + b_ih[2048 + jg] + b_hh[2048 + jg];
        float go = Cs[m * 33 + 24 + jj] + b_ih[3072 + jg] + b_hh[3072 + jg];
        float si = 1.f / (1.f + expf(-gi));
        float sf = 1.f / (1.f + expf(-gf));
        float so = 1.f / (1.f + expf(-go));
        float cn = sf * c_st[(size_t)m * Hh + jg] + si * tanhf(gg);
        c_st[(size_t)m * Hh + jg] = cn;
        float hn = so * tanhf(cn);
        // packed, pre-swizzled write
        uint32_t o = (uint32_t)(m * 128 + (jg & 63) * 2);
        uint32_t so_ = o ^ ((uint32_t)(m & 7) << 4);
        *(bf16*)((char*)hP + (size_t)hchunk * A_BYTES + so_) = __float2bfloat16_rn(hn);
        if (h_f) h_f[(size_t)m * Hh + jg] = hn;
    }
}

// ---------------- the single persistent decoder kernel ----------------
__global__ void __launch_bounds__(256, 1) decoder_kernel(
    const int* __restrict__ labels, const float* __restrict__ keys,
    const float* __restrict__ values, const float* __restrict__ emb,
    const float* __restrict__ w_ih0, const float* __restrict__ w_hh0,
    const float* __restrict__ b_ih0, const float* __restrict__ b_hh0,
    const float* __restrict__ w_ih1, const float* __restrict__ w_hh1,
    const float* __restrict__ b_ih1, const float* __restrict__ b_hh1,
    const float* __restrict__ w_ih2, const float* __restrict__ w_hh2,
    const float* __restrict__ b_ih2, const float* __restrict__ b_hh2,
    const float* __restrict__ w_proj, const float* __restrict__ b_proj,
    const float* __restrict__ w_score, const float* __restrict__ b_score,
    const float* __restrict__ h0,
    float* __restrict__ out_pred, float* __restrict__ out_attn)
{
    extern __shared__ __align__(128) char smem_raw[];
    const int tid = threadIdx.x;
    const int cta = blockIdx.x;
    const int lane = tid & 31;
    const int wid = tid >> 5;

    const unsigned ep0 = *(volatile unsigned*)&g_epoch;
    unsigned nbar = 0;

    // ---- mbarrier one-time init (count = 1 arrival per fill, by tid 0) ----
    {
        const uint32_t smem_u = (uint32_t)__cvta_generic_to_shared(smem_raw);
        if (tid < STAGES) mbar_init(smem_u + MBAR_OFF + tid * 8, 1);
        fence_proxy_async_cta();
        __syncthreads();
    }

    // ================= PREP =================
    {
        const float* wih[3] = {w_ih0, w_ih1, w_ih2};
        const float* whh[3] = {w_hh0, w_hh1, w_hh2};
        // weight pack: tile idx = ((cell*128 + c)*32 + kt), 4096 B each
        for (int idx = cta; idx < 3 * 128 * 32; idx += NCTA) {
            int cell = idx >> 12;
            int rem = idx & 4095;
            int c = rem >> 5;
            int kt = rem & 31;
            int n = tid >> 3;               // 0..31
            int kp0 = (tid & 7) * 8;        // 0..56
            int g = n >> 3;
            int r = g * 1024 + c * 8 + (n & 7);
            const float* src = (kt < 16 ? wih[cell] : whh[cell])
                + (size_t)r * 1024 + (kt & 15) * 64 + kp0;
            float4 v0 = ((const float4*)src)[0];
            float4 v1 = ((const float4*)src)[1];
            char* dtile = (char*)g_wP + (size_t)idx * B_BYTES;
            uint32_t o = (uint32_t)(n * 128 + kp0 * 2);
            uint32_t so = o ^ ((uint32_t)(n & 7) << 4);
            __nv_bfloat162* d = (__nv_bfloat162*)(dtile + so);
            d[0] = __floats2bfloat162_rn(v0.x, v0.y);
            d[1] = __floats2bfloat162_rn(v0.z, v0.w);
            d[2] = __floats2bfloat162_rn(v1.x, v1.y);
            d[3] = __floats2bfloat162_rn(v1.z, v1.w);
        }
        // embedding -> packed xs
        for (int tb = cta; tb < Tt * Bsz; tb += NCTA) {
            int t = tb / Bsz, b = tb % Bsz;
            int lab = labels[b * Tt + t];
            if (tid < 128) {
                int e0 = tid * 4;
                int ktc = e0 >> 6;
                float4 v = ((const float4*)(emb + (size_t)lab * Ee))[tid];
                char* dst = (char*)g_xsP + ((size_t)t * 8 + ktc) * A_BYTES;
                uint32_t o = (uint32_t)(b * 128 + (e0 & 63) * 2);
                uint32_t so = o ^ ((uint32_t)(b & 7) << 4);
                __nv_bfloat162* d = (__nv_bfloat162*)(dst + so);
                d[0] = __floats2bfloat162_rn(v.x, v.y);
                d[1] = __floats2bfloat162_rn(v.z, v.w);
            }
        }
        // init h/c (+ packed h)
#pragma unroll
        for (int j = 0; j < 2; j++) {
            int i = cta * 512 + j * 256 + tid;
            int b = i >> 10, jj = i & 1023;
            float v = h0[jj];
            bf16 vb = __float2bfloat16_rn(v);
            uint32_t o = (uint32_t)(b * 128 + (jj & 63) * 2);
            uint32_t so = o ^ ((uint32_t)(b & 7) << 4);
            size_t toff = (size_t)(jj >> 6) * A_BYTES + so;
            *(bf16*)((char*)g_h1P[0] + toff) = vb;
            *(bf16*)((char*)g_h2P[0] + toff) = vb;
            *(bf16*)((char*)g_h3P[0] + toff) = vb;
            g_h3f[0][i] = v;
            g_c1[i] = v; g_c2[i] = v; g_c3[i] = v;
        }
        // zero out_pred
        for (int i = cta * 256 + tid; i < Bsz * Tt * Vv; i += NCTA * 256)
            out_pred[i] = 0.f;
        // ctx0 -> packed
        float* red = (float*)smem_raw;
        for (int kk = 0; kk < 4; kk++) {
            int k = cta * 4 + kk;
            float s = 0.f;
            for (int i = tid; i < Hh; i += 256)
                s += h0[i] * w_proj[(size_t)k * Hh + i];
#pragma unroll
            for (int off = 16; off; off >>= 1)
                s += __shfl_xor_sync(0xffffffffu, s, off);
            if (lane == 0) red[wid] = s;
            __syncthreads();
            if (tid == 0) {
                float v = 0.f;
#pragma unroll
                for (int j = 0; j < 8; j++) v += red[j];
                red[8] = v + b_proj[k];
            }
            __syncthreads();
            float v = red[8];
            if (tid < Bsz) {
                uint32_t o = (uint32_t)(tid * 128 + (k & 63) * 2);
                uint32_t so = o ^ ((uint32_t)(tid & 7) << 4);
                *(bf16*)((char*)g_ctxP + (size_t)(k >> 6) * A_BYTES + so) =
                    __float2bfloat16_rn(v);
            }
            __syncthreads();
        }
    }
    grid_bar(ep0 + ++nbar);

    // ================= TIME LOOP =================
    for (int t = 0; t < Tt; t++) {
        lstm_phase(smem_raw, 0, t, 3 * t + 0, b_ih0, b_hh0);
        grid_bar(ep0 + ++nbar);
        lstm_phase(smem_raw, 1, t, 3 * t + 1, b_ih1, b_hh1);
        grid_bar(ep0 + ++nbar);
        lstm_phase(smem_raw, 2, t, 3 * t + 2, b_ih2, b_hh2);
        grid_bar(ep0 + ++nbar);

        // ---- proj: q = h3 @ w_proj^T + b_proj (kb = cta, 4 k's) ----
        {
            float* sw = (float*)smem_raw;
            const float4* wp4 = (const float4*)(w_proj + (size_t)cta * 4 * 1024);
            float4* sw4 = (float4*)sw;
#pragma unroll
            for (int j = 0; j < 4; j++) sw4[tid + j * 256] = wp4[tid + j * 256];
            __syncthreads();

            const float* h3 = g_h3f[1 - (t & 1)];
            int b = tid >> 2;
            int kl = tid & 3;
            const float4* hr = (const float4*)(h3 + (size_t)b * Hh);
            const float4* w0 = (const float4*)(sw + kl * 1024);
            float a0 = 0.f, a1 = 0.f;
#pragma unroll 4
            for (int i = 0; i < 256; i += 2) {
                float4 h4 = hr[i];
                float4 x0 = w0[i];
                a0 += h4.x * x0.x + h4.y * x0.y + h4.z * x0.z + h4.w * x0.w;
                float4 h5 = hr[i + 1];
                float4 x1 = w0[i + 1];
                a1 += h5.x * x1.x + h5.y * x1.y + h5.z * x1.z + h5.w * x1.w;
            }
            int kg = cta * 4 + kl;
            g_q[(size_t)b * Kk + kg] = a0 + a1 + b_proj[kg];
        }
        grid_bar(ep0 + ++nbar);

        // ---- energy ----
        {
            float* sq = (float*)smem_raw;
            const int b = cta & 63;
            const int half = cta >> 6;
            if (tid < 128)
                ((float4*)sq)[tid] = ((const float4*)(g_q + (size_t)b * Kk))[tid];
            __syncthreads();
            const float4* qr = (const float4*)sq;
            const int base = half * 200;
#pragma unroll 2
            for (int i = 0; i < 12; i++) {
                int s1 = base + wid + 16 * i;
                int s2 = s1 + 8;
                const float4* k1 = (const float4*)(keys + ((size_t)s1 * Bsz + b) * Kk);
                const float4* k2 = (const float4*)(keys + ((size_t)s2 * Bsz + b) * Kk);
                float acc1 = 0.f, acc2 = 0.f;
#pragma unroll
                for (int u = 0; u < 4; u++) {
                    float4 q4 = qr[lane + u * 32];
                    float4 a4 = k1[lane + u * 32];
                    float4 b4 = k2[lane + u * 32];
                    acc1 += a4.x * q4.x + a4.y * q4.y + a4.z * q4.z + a4.w * q4.w;
                    acc2 += b4.x * q4.x + b4.y * q4.y + b4.z * q4.z + b4.w * q4.w;
                }
#pragma unroll
                for (int off = 16; off; off >>= 1) {
                    acc1 += __shfl_xor_sync(0xffffffffu, acc1, off);
                    acc2 += __shfl_xor_sync(0xffffffffu, acc2, off);
                }
                if (lane == 0) {
                    g_energy[b * Ss + s1] = acc1;
                    g_energy[b * Ss + s2] = acc2;
                }
            }
            {
                int s = base + 192 + wid;
                const float4* kr = (const float4*)(keys + ((size_t)s * Bsz + b) * Kk);
                float acc = 0.f;
#pragma unroll
                for (int u = 0; u < 4; u++) {
                    float4 k4 = kr[lane + u * 32];
                    float4 q4 = qr[lane + u * 32];
                    acc += k4.x * q4.x + k4.y * q4.y + k4.z * q4.z + k4.w * q4.w;
                }
#pragma unroll
                for (int off = 16; off; off >>= 1)
                    acc += __shfl_xor_sync(0xffffffffu, acc, off);
                if (lane == 0) g_energy[b * Ss + s] = acc;
            }
            __syncthreads();
        }
        grid_bar(ep0 + ++nbar);

        // ---- softmax + ctx + partial score ----
        {
            float* sattn = (float*)smem_raw;
            float* sctx  = sattn + Ss;
            float* sqh   = sctx + 256;
            float* red   = sqh + 256;
            const int b = cta & 63;
            const int half = cta >> 6;
            const int koff = half * 256;

            for (int s = tid; s < Ss; s += 256) sattn[s] = g_energy[b * Ss + s];
            sqh[tid] = g_q[(size_t)b * Kk + koff + tid];
            __syncthreads();

            float m = -3.4e38f;
            for (int s = tid; s < Ss; s += 256) m = fmaxf(m, sattn[s]);
#pragma unroll
            for (int off = 16; off; off >>= 1)
                m = fmaxf(m, __shfl_xor_sync(0xffffffffu, m, off));
            if (lane == 0) red[wid] = m;
            __syncthreads();
            if (wid == 0) {
                float v = (lane < 8) ? red[lane] : -3.4e38f;
#pragma unroll
                for (int off = 4; off; off >>= 1)
                    v = fmaxf(v, __shfl_xor_sync(0xffffffffu, v, off));
                if (lane == 0) red[8] = v;
            }
            __syncthreads();
            const float mx = red[8];
            __syncthreads();

            float sum = 0.f;
            for (int s = tid; s < Ss; s += 256) {
                float e = expf(sattn[s] - mx);
                sattn[s] = e;
                sum += e;
            }
#pragma unroll
            for (int off = 16; off; off >>= 1)
                sum += __shfl_xor_sync(0xffffffffu, sum, off);
            if (lane == 0) red[wid] = sum;
            __syncthreads();
            if (wid == 0) {
                float v = (lane < 8) ? red[lane] : 0.f;
#pragma unroll
                for (int off = 4; off; off >>= 1)
                    v += __shfl_xor_sync(0xffffffffu, v, off);
                if (lane == 0) red[8] = v;
            }
            __syncthreads();
            const float inv = 1.f / red[8];
            for (int s = tid; s < Ss; s += 256) sattn[s] *= inv;
            __syncthreads();

            for (int s = half * 200 + tid; s < half * 200 + 200; s += 256)
                out_attn[((size_t)b * Tt + t) * Ss + s] = sattn[s];

            // ctx for k in [koff, koff+256), fp32 values; write packed bf16
            {
                const int k = koff + tid;
                const size_t base = (size_t)b * Kk + k;
                const size_t str = (size_t)Bsz * Kk;
                float a0 = 0.f, a1 = 0.f, a2 = 0.f, a3 = 0.f;
                for (int s = 0; s < Ss; s += 4) {
                    a0 += sattn[s]     * values[base + (size_t)s * str];
                    a1 += sattn[s + 1] * values[base + (size_t)(s + 1) * str];
                    a2 += sattn[s + 2] * values[base + (size_t)(s + 2) * str];
                    a3 += sattn[s + 3] * values[base + (size_t)(s + 3) * str];
                }
                float r = (a0 + a1) + (a2 + a3);
                sctx[tid] = r;
                uint32_t o = (uint32_t)(b * 128 + (k & 63) * 2);
                uint32_t so = o ^ ((uint32_t)(b & 7) << 4);
                *(bf16*)((char*)g_ctxP + (size_t)(k >> 6) * A_BYTES + so) =
                    __float2bfloat16_rn(r);
            }
            __syncthreads();

            for (int v = wid; v < Vv; v += 8) {
                const float* wr = w_score + (size_t)v * (2 * Kk);
                float acc = 0.f;
                for (int i = lane; i < 256; i += 32)
                    acc += sqh[i] * wr[koff + i] + sctx[i] * wr[Kk + koff + i];
#pragma unroll
                for (int off = 16; off; off >>= 1)
                    acc += __shfl_xor_sync(0xffffffffu, acc, off);
                if (lane == 0) {
                    float add = acc + (half == 0 ? b_score[v] : 0.f);
                    atomicAdd(&out_pred[((size_t)b * Tt + t) * Vv + v], add);
                }
            }
            __syncthreads();
        }
        grid_bar(ep0 + ++nbar);
    }
}

// ---------------- launch ----------------
extern "C" void kernel_launch(void* const* d_in, const int* in_sizes, int n_in,
                              void* d_out, int out_size) {
    const int*   labels  = (const int*)  d_in[0];
    const float* keys    = (const float*)d_in[1];
    const float* values  = (const float*)d_in[2];
    const float* emb     = (const float*)d_in[3];
    const float* w_ih0   = (const float*)d_in[4];
    const float* w_hh0   = (const float*)d_in[5];
    const float* b_ih0   = (const float*)d_in[6];
    const float* b_hh0   = (const float*)d_in[7];
    const float* w_ih1   = (const float*)d_in[8];
    const float* w_hh1   = (const float*)d_in[9];
    const float* b_ih1   = (const float*)d_in[10];
    const float* b_hh1   = (const float*)d_in[11];
    const float* w_ih2   = (const float*)d_in[12];
    const float* w_hh2   = (const float*)d_in[13];
    const float* b_ih2   = (const float*)d_in[14];
    const float* b_hh2   = (const float*)d_in[15];
    const float* w_proj  = (const float*)d_in[16];
    const float* b_proj  = (const float*)d_in[17];
    const float* w_score = (const float*)d_in[18];
    const float* b_score = (const float*)d_in[19];
    const float* h0      = (const float*)d_in[20];

    float* out_pred = (float*)d_out;
    float* out_attn = out_pred + (size_t)Bsz * Tt * Vv;

    static int configured = 0;
    if (!configured) {
        cudaFuncSetAttribute(decoder_kernel,
                             cudaFuncAttributeMaxDynamicSharedMemorySize, SMEM_TOTAL);
        configured = 1;
    }

    decoder_kernel<<<NCTA, 256, SMEM_TOTAL>>>(
        labels, keys, values, emb,
        w_ih0, w_hh0, b_ih0, b_hh0,
        w_ih1, w_hh1, b_ih1, b_hh1,
        w_ih2, w_hh2, b_ih2, b_hh2,
        w_proj, b_proj, w_score, b_score, h0,
        out_pred, out_attn);
}

// round 15
// speedup vs baseline: 2.0028x; 1.1276x over previous
#include <cuda_runtime.h>
#include <cuda_bf16.h>
#include <math.h>
#include <stdint.h>
#include <stddef.h>

#define Bsz 64
#define Tt  100
#define Ss  400
#define Ee  512
#define Hh  1024
#define Kk  512
#define Vv  34

#define NCTA 128

typedef __nv_bfloat16 bf16;

// ---------------- static device scratch ----------------
__device__ __align__(256) bf16  g_wcat[3][(size_t)4096 * 2048];  // bf16 weights, concat ih|hh
__device__ __align__(256) bf16  g_xs[(size_t)Tt * Bsz * Ee];     // bf16 embedded inputs
__device__ __align__(256) bf16  g_h1b[2][Bsz * Hh];              // bf16 h states (ping-pong)
__device__ __align__(256) bf16  g_h2b[2][Bsz * Hh];
__device__ __align__(256) bf16  g_h3b[2][Bsz * Hh];
__device__ __align__(256) float g_h3f[2][Bsz * Hh];              // fp32 h3 (for proj)
__device__ __align__(256) float g_c1[Bsz * Hh];
__device__ __align__(256) float g_c2[Bsz * Hh];
__device__ __align__(256) float g_c3[Bsz * Hh];
__device__ __align__(256) bf16  g_ctxb[Bsz * Kk];                // bf16 (gemm input)
__device__ __align__(256) float g_q[Bsz * Kk];
__device__ __align__(256) float g_energy[Bsz * Ss];

// grid barrier state (monotonic epoch; survives replays correctly)
__device__ unsigned g_cnt = 0;
__device__ unsigned g_epoch = 0;

// ---------------- helpers ----------------
__device__ __forceinline__ void cpa16(uint32_t dst, const void* src) {
    asm volatile("cp.async.ca.shared.global [%0], [%1], 16;\n" :: "r"(dst), "l"(src));
}
// evict-first variant: streamed data (weights) should not evict resident K/V
__device__ __forceinline__ void cpa16_ef(uint32_t dst, const void* src, uint64_t pol) {
    asm volatile("cp.async.ca.shared.global.L2::cache_hint [%0], [%1], 16, %2;\n"
                 :: "r"(dst), "l"(src), "l"(pol));
}
#define CPA_COMMIT() asm volatile("cp.async.commit_group;\n" ::: "memory")
#define CPA_WAIT(n)  asm volatile("cp.async.wait_group %0;\n" :: "n"(n) : "memory")

__device__ __forceinline__ void mma_bf16(float* c,
    uint32_t a0, uint32_t a1, uint32_t a2, uint32_t a3,
    uint32_t b0, uint32_t b1) {
    asm volatile(
        "mma.sync.aligned.m16n8k16.row.col.f32.bf16.bf16.f32 "
        "{%0,%1,%2,%3},{%4,%5,%6,%7},{%8,%9},{%0,%1,%2,%3};\n"
        : "+f"(c[0]), "+f"(c[1]), "+f"(c[2]), "+f"(c[3])
        : "r"(a0), "r"(a1), "r"(a2), "r"(a3), "r"(b0), "r"(b1));
}

__device__ __forceinline__ void ldsm4(uint32_t& r0, uint32_t& r1,
                                      uint32_t& r2, uint32_t& r3, uint32_t addr) {
    asm volatile("ldmatrix.sync.aligned.m8n8.x4.shared.b16 {%0,%1,%2,%3}, [%4];"
        : "=r"(r0), "=r"(r1), "=r"(r2), "=r"(r3) : "r"(addr));
}

// grid-wide barrier, CG-style: fences only in the elected thread.
// __syncthreads provides the intra-CTA happens-before edge; thread 0's
// cumulative __threadfence releases ALL CTA threads' prior writes; the
// trailing fence is the acquire (CCTL.IVALL invalidates this SM's L1D).
__device__ __forceinline__ void grid_bar(unsigned target) {
    __syncthreads();
    if (threadIdx.x == 0) {
        __threadfence();     // release (cumulative)
        unsigned n = atomicAdd(&g_cnt, 1u);
        if (n == NCTA - 1u) {
            g_cnt = 0;
            __threadfence();
            atomicAdd(&g_epoch, 1u);
        } else {
            while (*(volatile unsigned*)&g_epoch < target) __nanosleep(32);
        }
        __threadfence();     // acquire + L1D invalidate
    }
    __syncthreads();
}

// ---------------- LSTM tiling constants ----------------
#define BK 64
#define STAGES 7
#define PFD 5
#define APAD 72
#define A_ST (64 * APAD)
#define B_ST (32 * APAD)
#define STAGE_ELE (A_ST + B_ST)
#define LSTM_SMEM (STAGES * STAGE_ELE * 2)

struct SegInfo { const bf16* p; int stride; };

__device__ __forceinline__ SegInfo a_seg(int cell, int p, int t, int seg) {
    SegInfo r;
    if (cell == 0) {
        if (seg == 0)      { r.p = g_xs + (size_t)t * Bsz * Ee; r.stride = Ee; }
        else if (seg == 1) { r.p = g_ctxb;                      r.stride = Kk; }
        else               { r.p = g_h1b[p] + (seg - 2) * 512;  r.stride = Hh; }
    } else if (cell == 1) {
        if (seg < 2) { r.p = g_h1b[1 - p] + seg * 512;       r.stride = Hh; }
        else         { r.p = g_h2b[p]     + (seg - 2) * 512; r.stride = Hh; }
    } else {
        if (seg < 2) { r.p = g_h2b[1 - p] + seg * 512;       r.stride = Hh; }
        else         { r.p = g_h3b[p]     + (seg - 2) * 512; r.stride = Hh; }
    }
    return r;
}

// ---------------- lstm phase (runs on all 128 CTAs) ----------------
__device__ __forceinline__ void lstm_phase(
    char* smem_raw, int cell, int t,
    const float* __restrict__ b_ih, const float* __restrict__ b_hh)
{
    bf16* smem = (bf16*)smem_raw;
    const int p = t & 1;
    const int tid = threadIdx.x;
    const int lane = tid & 31;
    const int warp = tid >> 5;
    const int wm = warp & 3;
    const int wn = warp >> 2;
    const int j0 = blockIdx.x * 8;
    const bf16* __restrict__ wcat = g_wcat[cell];

    uint64_t pol;
    asm("createpolicy.fractional.L2::evict_first.b64 %0;" : "=l"(pol));

    float* c_st; bf16* h_ob; float* h_f;
    if (cell == 0)      { c_st = g_c1; h_ob = g_h1b[1 - p]; h_f = nullptr; }
    else if (cell == 1) { c_st = g_c2; h_ob = g_h2b[1 - p]; h_f = nullptr; }
    else                { c_st = g_c3; h_ob = g_h3b[1 - p]; h_f = g_h3f[1 - p]; }

    const uint32_t smem_u = (uint32_t)__cvta_generic_to_shared(smem);

    float acc0[4] = {0.f, 0.f, 0.f, 0.f};
    float acc1[4] = {0.f, 0.f, 0.f, 0.f};

    const int NTILES = 2048 / BK;

    auto issue_tile = [&](int kt, int ss) {
        const int k0 = kt * BK;
        SegInfo si = a_seg(cell, p, t, k0 >> 9);
        const int kin = k0 & 511;
        const uint32_t abase = smem_u + (uint32_t)(ss * STAGE_ELE) * 2u;
        const uint32_t bbase = abase + (uint32_t)A_ST * 2u;
#pragma unroll
        for (int j = 0; j < 2; j++) {
            int i = tid + j * 256;
            int m = i >> 3, c8 = i & 7;
            const bf16* src = si.p + (size_t)m * si.stride + kin + c8 * 8;
            cpa16(abase + (uint32_t)(m * APAD + c8 * 8) * 2u, src);
        }
        {
            int n = tid >> 3, c8 = tid & 7;
            int r = (n >> 3) * 1024 + j0 + (n & 7);
            const bf16* src = wcat + (size_t)r * 2048 + k0 + c8 * 8;
            cpa16_ef(bbase + (uint32_t)(n * APAD + c8 * 8) * 2u, src, pol);
        }
    };

#pragma unroll
    for (int i = 0; i < PFD; i++) { issue_tile(i, i); CPA_COMMIT(); }

    const uint32_t a_lane_off =
        (uint32_t)((wm * 16 + (lane & 15)) * APAD + (lane >> 4) * 8) * 2u;
    const uint32_t b_lane_off =
        (uint32_t)((wn * 16 + ((lane >> 4) << 3) + (lane & 7)) * APAD
                   + ((lane >> 3) & 1) * 8) * 2u;

    for (int kt = 0; kt < NTILES; kt++) {
        if (kt + PFD < NTILES) issue_tile(kt + PFD, (kt + PFD) % STAGES);
        CPA_COMMIT();
        CPA_WAIT(PFD);
        __syncthreads();

        const uint32_t As_u = smem_u + (uint32_t)((kt % STAGES) * STAGE_ELE) * 2u;
        const uint32_t Bs_u = As_u + (uint32_t)A_ST * 2u;
#pragma unroll
        for (int ks = 0; ks < BK / 16; ks++) {
            const uint32_t kb2 = (uint32_t)(ks * 16) * 2u;
            uint32_t a0, a1, a2, a3, b0, b1, b2, b3;
            ldsm4(a0, a1, a2, a3, As_u + a_lane_off + kb2);
            ldsm4(b0, b1, b2, b3, Bs_u + b_lane_off + kb2);
            mma_bf16(acc0, a0, a1, a2, a3, b0, b1);
            mma_bf16(acc1, a0, a1, a2, a3, b2, b3);
        }
    }
    CPA_WAIT(0);
    __syncthreads();

    float* Cs = (float*)smem_raw;
    {
        const int ar = lane >> 2;
        const int ac = lane & 3;
        int crow = wm * 16 + ar;
        int cc0 = wn * 16 + 2 * ac;
        Cs[crow * 33 + cc0]           = acc0[0];
        Cs[crow * 33 + cc0 + 1]       = acc0[1];
        Cs[(crow + 8) * 33 + cc0]     = acc0[2];
        Cs[(crow + 8) * 33 + cc0 + 1] = acc0[3];
        Cs[crow * 33 + cc0 + 8]       = acc1[0];
        Cs[crow * 33 + cc0 + 9]       = acc1[1];
        Cs[(crow + 8) * 33 + cc0 + 8] = acc1[2];
        Cs[(crow + 8) * 33 + cc0 + 9] = acc1[3];
    }
    __syncthreads();

#pragma unroll
    for (int j = 0; j < 2; j++) {
        int pr = tid + j * 256;
        int m = pr & 63;
        int jj = pr >> 6;
        int jg = j0 + jj;
        float gi = Cs[m * 33 + jj]      + b_ih[jg]        + b_hh[jg];
        float gf = Cs[m * 33 + 8 + jj]  + b_ih[1024 + jg] + b_hh[1024 + jg];
        float gg = Cs[m * 33 + 16 + jj] + b_ih[2048 + jg] + b_hh[2048 + jg];
        float go = Cs[m * 33 + 24 + jj] + b_ih[3072 + jg] + b_hh[3072 + jg];
        float si = 1.f / (1.f + expf(-gi));
        float sf = 1.f / (1.f + expf(-gf));
        float so = 1.f / (1.f + expf(-go));
        float cn = sf * c_st[(size_t)m * Hh + jg] + si * tanhf(gg);
        c_st[(size_t)m * Hh + jg] = cn;
        float hn = so * tanhf(cn);
        h_ob[(size_t)m * Hh + jg] = __float2bfloat16_rn(hn);
        if (h_f) h_f[(size_t)m * Hh + jg] = hn;
    }
}

// ---------------- the single persistent decoder kernel ----------------
__global__ void __launch_bounds__(256, 1) decoder_kernel(
    const int* __restrict__ labels, const float* __restrict__ keys,
    const float* __restrict__ values, const float* __restrict__ emb,
    const float* __restrict__ w_ih0, const float* __restrict__ w_hh0,
    const float* __restrict__ b_ih0, const float* __restrict__ b_hh0,
    const float* __restrict__ w_ih1, const float* __restrict__ w_hh1,
    const float* __restrict__ b_ih1, const float* __restrict__ b_hh1,
    const float* __restrict__ w_ih2, const float* __restrict__ w_hh2,
    const float* __restrict__ b_ih2, const float* __restrict__ b_hh2,
    const float* __restrict__ w_proj, const float* __restrict__ b_proj,
    const float* __restrict__ w_score, const float* __restrict__ b_score,
    const float* __restrict__ h0,
    float* __restrict__ out_pred, float* __restrict__ out_attn)
{
    extern __shared__ __align__(16) char smem_raw[];
    const int tid = threadIdx.x;
    const int cta = blockIdx.x;
    const int lane = tid & 31;
    const int wid = tid >> 5;

    const unsigned ep0 = *(volatile unsigned*)&g_epoch;
    unsigned nbar = 0;

    // ================= PREP =================
    {
        const float* wih[3] = {w_ih0, w_ih1, w_ih2};
        const float* whh[3] = {w_hh0, w_hh1, w_hh2};
        for (int r = cta; r < 3 * 4096; r += NCTA) {
            int cell = r >> 12, row = r & 4095;
            float4 va = ((const float4*)(wih[cell] + (size_t)row * 1024))[tid];
            float4 vb = ((const float4*)(whh[cell] + (size_t)row * 1024))[tid];
            __nv_bfloat162* d2 = (__nv_bfloat162*)(g_wcat[cell] + (size_t)row * 2048);
            d2[2 * tid]           = __floats2bfloat162_rn(va.x, va.y);
            d2[2 * tid + 1]       = __floats2bfloat162_rn(va.z, va.w);
            d2[512 + 2 * tid]     = __floats2bfloat162_rn(vb.x, vb.y);
            d2[512 + 2 * tid + 1] = __floats2bfloat162_rn(vb.z, vb.w);
        }
        // embedding
        for (int tb = cta; tb < Tt * Bsz; tb += NCTA) {
            int t = tb / Bsz, b = tb % Bsz;
            int lab = labels[b * Tt + t];
            if (tid < 128) {
                float4 v = ((const float4*)(emb + (size_t)lab * Ee))[tid];
                __nv_bfloat162* dst =
                    (__nv_bfloat162*)(g_xs + ((size_t)t * Bsz + b) * Ee);
                dst[2 * tid]     = __floats2bfloat162_rn(v.x, v.y);
                dst[2 * tid + 1] = __floats2bfloat162_rn(v.z, v.w);
            }
        }
        // init h/c
#pragma unroll
        for (int j = 0; j < 2; j++) {
            int i = cta * 512 + j * 256 + tid;
            float v = h0[i & (Hh - 1)];
            bf16 vb = __float2bfloat16_rn(v);
            g_h1b[0][i] = vb; g_h2b[0][i] = vb; g_h3b[0][i] = vb;
            g_h3f[0][i] = v;
            g_c1[i] = v; g_c2[i] = v; g_c3[i] = v;
        }
        // zero out_pred (atomicAdd target)
        for (int i = cta * 256 + tid; i < Bsz * Tt * Vv; i += NCTA * 256)
            out_pred[i] = 0.f;
        // ctx0
        float* red = (float*)smem_raw;
        for (int kk = 0; kk < 4; kk++) {
            int k = cta * 4 + kk;
            float s = 0.f;
            for (int i = tid; i < Hh; i += 256)
                s += h0[i] * w_proj[(size_t)k * Hh + i];
#pragma unroll
            for (int off = 16; off; off >>= 1)
                s += __shfl_xor_sync(0xffffffffu, s, off);
            if (lane == 0) red[wid] = s;
            __syncthreads();
            if (tid == 0) {
                float v = 0.f;
#pragma unroll
                for (int j = 0; j < 8; j++) v += red[j];
                red[8] = v + b_proj[k];
            }
            __syncthreads();
            float v = red[8];
            if (tid < Bsz) g_ctxb[(size_t)tid * Kk + k] = __float2bfloat16_rn(v);
            __syncthreads();
        }
    }
    grid_bar(ep0 + ++nbar);

    // ================= TIME LOOP =================
    for (int t = 0; t < Tt; t++) {
        lstm_phase(smem_raw, 0, t, b_ih0, b_hh0);
        grid_bar(ep0 + ++nbar);
        lstm_phase(smem_raw, 1, t, b_ih1, b_hh1);
        grid_bar(ep0 + ++nbar);
        lstm_phase(smem_raw, 2, t, b_ih2, b_hh2);
        grid_bar(ep0 + ++nbar);

        // ---- proj: q = h3 @ w_proj^T + b_proj (kb = cta, 4 k's) ----
        {
            float* sw = (float*)smem_raw;
            const float4* wp4 = (const float4*)(w_proj + (size_t)cta * 4 * 1024);
            float4* sw4 = (float4*)sw;
#pragma unroll
            for (int j = 0; j < 4; j++) sw4[tid + j * 256] = wp4[tid + j * 256];
            __syncthreads();

            const float* h3 = g_h3f[1 - (t & 1)];
            int b = tid >> 2;
            int kl = tid & 3;
            const float4* hr = (const float4*)(h3 + (size_t)b * Hh);
            const float4* w0 = (const float4*)(sw + kl * 1024);
            float a0 = 0.f, a1 = 0.f;
#pragma unroll 4
            for (int i = 0; i < 256; i += 2) {
                float4 h4 = hr[i];
                float4 x0 = w0[i];
                a0 += h4.x * x0.x + h4.y * x0.y + h4.z * x0.z + h4.w * x0.w;
                float4 h5 = hr[i + 1];
                float4 x1 = w0[i + 1];
                a1 += h5.x * x1.x + h5.y * x1.y + h5.z * x1.z + h5.w * x1.w;
            }
            int kg = cta * 4 + kl;
            g_q[(size_t)b * Kk + kg] = a0 + a1 + b_proj[kg];
        }
        grid_bar(ep0 + ++nbar);

        // ---- energy: cta -> (b = cta&63, half = cta>>6), 200 s each ----
        {
            float* sq = (float*)smem_raw;
            const int b = cta & 63;
            const int half = cta >> 6;
            if (tid < 128)
                ((float4*)sq)[tid] = ((const float4*)(g_q + (size_t)b * Kk))[tid];
            __syncthreads();
            const float4* qr = (const float4*)sq;
            const int base = half * 200;
#pragma unroll 2
            for (int i = 0; i < 12; i++) {
                int s1 = base + wid + 16 * i;
                int s2 = s1 + 8;
                const float4* k1 = (const float4*)(keys + ((size_t)s1 * Bsz + b) * Kk);
                const float4* k2 = (const float4*)(keys + ((size_t)s2 * Bsz + b) * Kk);
                float acc1 = 0.f, acc2 = 0.f;
#pragma unroll
                for (int u = 0; u < 4; u++) {
                    float4 q4 = qr[lane + u * 32];
                    float4 a4 = k1[lane + u * 32];
                    float4 b4 = k2[lane + u * 32];
                    acc1 += a4.x * q4.x + a4.y * q4.y + a4.z * q4.z + a4.w * q4.w;
                    acc2 += b4.x * q4.x + b4.y * q4.y + b4.z * q4.z + b4.w * q4.w;
                }
#pragma unroll
                for (int off = 16; off; off >>= 1) {
                    acc1 += __shfl_xor_sync(0xffffffffu, acc1, off);
                    acc2 += __shfl_xor_sync(0xffffffffu, acc2, off);
                }
                if (lane == 0) {
                    g_energy[b * Ss + s1] = acc1;
                    g_energy[b * Ss + s2] = acc2;
                }
            }
            {   // tail: s = base + 192 + wid
                int s = base + 192 + wid;
                const float4* kr = (const float4*)(keys + ((size_t)s * Bsz + b) * Kk);
                float acc = 0.f;
#pragma unroll
                for (int u = 0; u < 4; u++) {
                    float4 k4 = kr[lane + u * 32];
                    float4 q4 = qr[lane + u * 32];
                    acc += k4.x * q4.x + k4.y * q4.y + k4.z * q4.z + k4.w * q4.w;
                }
#pragma unroll
                for (int off = 16; off; off >>= 1)
                    acc += __shfl_xor_sync(0xffffffffu, acc, off);
                if (lane == 0) g_energy[b * Ss + s] = acc;
            }
            __syncthreads();
        }
        grid_bar(ep0 + ++nbar);

        // ---- softmax + ctx + partial score (cta -> b, half k-range) ----
        {
            float* sattn = (float*)smem_raw;          // 400
            float* sctx  = sattn + Ss;                 // 256
            float* sqh   = sctx + 256;                 // 256
            float* red   = sqh + 256;                  // 9
            const int b = cta & 63;
            const int half = cta >> 6;
            const int koff = half * 256;

            for (int s = tid; s < Ss; s += 256) sattn[s] = g_energy[b * Ss + s];
            sqh[tid] = g_q[(size_t)b * Kk + koff + tid];
            __syncthreads();

            // max
            float m = -3.4e38f;
            for (int s = tid; s < Ss; s += 256) m = fmaxf(m, sattn[s]);
#pragma unroll
            for (int off = 16; off; off >>= 1)
                m = fmaxf(m, __shfl_xor_sync(0xffffffffu, m, off));
            if (lane == 0) red[wid] = m;
            __syncthreads();
            if (wid == 0) {
                float v = (lane < 8) ? red[lane] : -3.4e38f;
#pragma unroll
                for (int off = 4; off; off >>= 1)
                    v = fmaxf(v, __shfl_xor_sync(0xffffffffu, v, off));
                if (lane == 0) red[8] = v;
            }
            __syncthreads();
            const float mx = red[8];
            __syncthreads();

            // exp + sum
            float sum = 0.f;
            for (int s = tid; s < Ss; s += 256) {
                float e = expf(sattn[s] - mx);
                sattn[s] = e;
                sum += e;
            }
#pragma unroll
            for (int off = 16; off; off >>= 1)
                sum += __shfl_xor_sync(0xffffffffu, sum, off);
            if (lane == 0) red[wid] = sum;
            __syncthreads();
            if (wid == 0) {
                float v = (lane < 8) ? red[lane] : 0.f;
#pragma unroll
                for (int off = 4; off; off >>= 1)
                    v += __shfl_xor_sync(0xffffffffu, v, off);
                if (lane == 0) red[8] = v;
            }
            __syncthreads();
            const float inv = 1.f / red[8];
            for (int s = tid; s < Ss; s += 256) sattn[s] *= inv;
            __syncthreads();

            // write attention output (this CTA's half of S)
            for (int s = half * 200 + tid; s < half * 200 + 200; s += 256)
                out_attn[((size_t)b * Tt + t) * Ss + s] = sattn[s];

            // ctx for k in [koff, koff+256), fp32 values
            {
                const int k = koff + tid;
                const size_t base = (size_t)b * Kk + k;
                const size_t str = (size_t)Bsz * Kk;
                float a0 = 0.f, a1 = 0.f, a2 = 0.f, a3 = 0.f;
                for (int s = 0; s < Ss; s += 4) {
                    a0 += sattn[s]     * values[base + (size_t)s * str];
                    a1 += sattn[s + 1] * values[base + (size_t)(s + 1) * str];
                    a2 += sattn[s + 2] * values[base + (size_t)(s + 2) * str];
                    a3 += sattn[s + 3] * values[base + (size_t)(s + 3) * str];
                }
                float r = (a0 + a1) + (a2 + a3);
                sctx[tid] = r;
                g_ctxb[(size_t)b * Kk + k] = __float2bfloat16_rn(r);
            }
            __syncthreads();

            // partial score over this k-half; combine across halves via atomicAdd
            for (int v = wid; v < Vv; v += 8) {
                const float* wr = w_score + (size_t)v * (2 * Kk);
                float acc = 0.f;
                for (int i = lane; i < 256; i += 32)
                    acc += sqh[i] * wr[koff + i] + sctx[i] * wr[Kk + koff + i];
#pragma unroll
                for (int off = 16; off; off >>= 1)
                    acc += __shfl_xor_sync(0xffffffffu, acc, off);
                if (lane == 0) {
                    float add = acc + (half == 0 ? b_score[v] : 0.f);
                    atomicAdd(&out_pred[((size_t)b * Tt + t) * Vv + v], add);
                }
            }
            __syncthreads();
        }
        grid_bar(ep0 + ++nbar);
    }
}

// ---------------- launch ----------------
extern "C" void kernel_launch(void* const* d_in, const int* in_sizes, int n_in,
                              void* d_out, int out_size) {
    const int*   labels  = (const int*)  d_in[0];
    const float* keys    = (const float*)d_in[1];
    const float* values  = (const float*)d_in[2];
    const float* emb     = (const float*)d_in[3];
    const float* w_ih0   = (const float*)d_in[4];
    const float* w_hh0   = (const float*)d_in[5];
    const float* b_ih0   = (const float*)d_in[6];
    const float* b_hh0   = (const float*)d_in[7];
    const float* w_ih1   = (const float*)d_in[8];
    const float* w_hh1   = (const float*)d_in[9];
    const float* b_ih1   = (const float*)d_in[10];
    const float* b_hh1   = (const float*)d_in[11];
    const float* w_ih2   = (const float*)d_in[12];
    const float* w_hh2   = (const float*)d_in[13];
    const float* b_ih2   = (const float*)d_in[14];
    const float* b_hh2   = (const float*)d_in[15];
    const float* w_proj  = (const float*)d_in[16];
    const float* b_proj  = (const float*)d_in[17];
    const float* w_score = (const float*)d_in[18];
    const float* b_score = (const float*)d_in[19];
    const float* h0      = (const float*)d_in[20];

    float* out_pred = (float*)d_out;
    float* out_attn = out_pred + (size_t)Bsz * Tt * Vv;

    static int configured = 0;
    if (!configured) {
        cudaFuncSetAttribute(decoder_kernel,
                             cudaFuncAttributeMaxDynamicSharedMemorySize, LSTM_SMEM);
        configured = 1;
    }

    decoder_kernel<<<NCTA, 256, LSTM_SMEM>>>(
        labels, keys, values, emb,
        w_ih0, w_hh0, b_ih0, b_hh0,
        w_ih1, w_hh1, b_ih1, b_hh1,
        w_ih2, w_hh2, b_ih2, b_hh2,
        w_proj, b_proj, w_score, b_score, h0,
        out_pred, out_attn);
}